// round 9
// baseline (speedup 1.0000x reference)
#include <cuda_runtime.h>
#include <cstdint>
#include <math_constants.h>

#define NPTS    65536
#define DIM     128
#define NC      512
#define MTILE   128
#define NTILES  (NPTS / MTILE)      // 512
#define NCHUNK  64                  // centroids per chunk
#define NCHUNKS (NC / NCHUNK)       // 8
#define THREADS 256
#define ZROW    132                 // padded z row stride (floats)

// Permuted-mu chunk in smem: 2048 float4 data in 9-stride padded slots
#define BUFSLOTS 2304               // (2048/8)*9
#define BUFBYTES (BUFSLOTS * 16)    // 36864
// SMEM: [buf0 | buf1 | sm2(512f) | sred(8f)]   (z stage aliases buf region)
#define OFF_SM2   (2 * BUFBYTES)
#define OFF_SRED  (OFF_SM2 + NC * 4)
#define SMEM_BYTES (OFF_SRED + 64)  // 75840

// Device scratch (no allocation allowed)
__device__ float4 g_mu_p[NC * 32];  // permuted tf32-rounded mu: (c*4+t)*8+kp
__device__ float  g_m2[NC];
__device__ float  g_partials[NTILES];

__device__ __forceinline__ uint32_t smem_u32(const void* p) {
    uint32_t a;
    asm("{ .reg .u64 t; cvta.to.shared.u64 t, %1; cvt.u32.u64 %0, t; }" : "=r"(a) : "l"(p));
    return a;
}
__device__ __forceinline__ uint32_t tf32_rna(float x) {
    uint32_t r;
    asm("cvt.rna.tf32.f32 %0, %1;" : "=r"(r) : "f"(x));
    return r;
}
__device__ __forceinline__ void mma_tf32(float* c, const uint32_t* a,
                                         uint32_t b0, uint32_t b1) {
    asm volatile(
        "mma.sync.aligned.m16n8k8.row.col.f32.tf32.tf32.f32 "
        "{%0,%1,%2,%3}, {%4,%5,%6,%7}, {%8,%9}, {%0,%1,%2,%3};"
        : "+f"(c[0]), "+f"(c[1]), "+f"(c[2]), "+f"(c[3])
        : "r"(a[0]), "r"(a[1]), "r"(a[2]), "r"(a[3]), "r"(b0), "r"(b1));
}
#define CP16(dst, src) \
    asm volatile("cp.async.cg.shared.global [%0], [%1], 16;" :: "r"(dst), "l"(src))
#define CP_COMMIT() asm volatile("cp.async.commit_group;" ::: "memory")
#define CP_WAIT(n)  asm volatile("cp.async.wait_group %0;" :: "n"(n) : "memory")

// ---------------------------------------------------------------------------
// prep: tf32-round mu into permuted layout + m2. One warp per centroid.
// lane -> (t = l&3, kp = l>>2). float4 = {mu[16kp+t], +4, +8, +12} rounded.
// ---------------------------------------------------------------------------
__global__ void prep_kernel(const float* __restrict__ mu) {
    int w = threadIdx.x >> 5, l = threadIdx.x & 31;
    int c = blockIdx.x * 8 + w;
    int t = l & 3, kp = l >> 2;
    const float* row = mu + (size_t)c * DIM;
    float a = __uint_as_float(tf32_rna(row[16 * kp + t]));
    float b = __uint_as_float(tf32_rna(row[16 * kp + t + 4]));
    float e = __uint_as_float(tf32_rna(row[16 * kp + t + 8]));
    float d = __uint_as_float(tf32_rna(row[16 * kp + t + 12]));
    g_mu_p[(size_t)c * 32 + t * 8 + kp] = make_float4(a, b, e, d);
    float s = a * a + b * b + e * e + d * d;
#pragma unroll
    for (int o = 16; o; o >>= 1) s += __shfl_xor_sync(0xFFFFFFFFu, s, o);
    if (l == 0) g_m2[c] = s;
}

// ---------------------------------------------------------------------------
// main: tf32 mma.sync GEMM with vectorized B frags + cp.async double buffer
// ---------------------------------------------------------------------------
__global__ void __launch_bounds__(THREADS, 2)
main_kernel(const float* __restrict__ z) {
    extern __shared__ __align__(16) char smem[];
    const uint32_t sb = smem_u32(smem);
    float* sm2  = reinterpret_cast<float*>(smem + OFF_SM2);
    float* sred = reinterpret_cast<float*>(smem + OFF_SRED);
    float* szf  = reinterpret_cast<float*>(smem);   // z stage aliases bufs

    const int tid = threadIdx.x, w = tid >> 5, lane = tid & 31;
    const int g = lane >> 2, t = lane & 3;
    const int mb = w * 16;

    // ---- stage z tile (raw) into padded smem via cp.async ----
    const float4* zt4 = reinterpret_cast<const float4*>(
        z + (size_t)blockIdx.x * MTILE * DIM);
#pragma unroll
    for (int j = 0; j < 16; j++) {
        int i = tid + j * THREADS;                 // float4 index, 0..4095
        int row = i >> 5, c4 = i & 31;
        CP16(sb + (uint32_t)(row * ZROW + c4 * 4) * 4, zt4 + i);
    }
    CP_COMMIT();
    // overlap: m2 table into smem
#pragma unroll
    for (int j = 0; j < 2; j++) sm2[tid + j * THREADS] = g_m2[tid + j * THREADS];
    CP_WAIT(0);
    __syncthreads();

    // ---- A fragments (tf32-rounded) + z2 from registers ----
    uint32_t A[16][4];
#pragma unroll
    for (int kk = 0; kk < 16; kk++) {
        A[kk][0] = tf32_rna(szf[(mb + g    ) * ZROW + kk * 8 + t    ]);
        A[kk][1] = tf32_rna(szf[(mb + g + 8) * ZROW + kk * 8 + t    ]);
        A[kk][2] = tf32_rna(szf[(mb + g    ) * ZROW + kk * 8 + t + 4]);
        A[kk][3] = tf32_rna(szf[(mb + g + 8) * ZROW + kk * 8 + t + 4]);
    }
    float z2a = 0.f, z2b = 0.f;
#pragma unroll
    for (int kk = 0; kk < 16; kk++) {
        float a0 = __uint_as_float(A[kk][0]), a2 = __uint_as_float(A[kk][2]);
        float a1 = __uint_as_float(A[kk][1]), a3 = __uint_as_float(A[kk][3]);
        z2a += a0 * a0 + a2 * a2;
        z2b += a1 * a1 + a3 * a3;
    }
    z2a += __shfl_xor_sync(0xFFFFFFFFu, z2a, 1);
    z2a += __shfl_xor_sync(0xFFFFFFFFu, z2a, 2);
    z2b += __shfl_xor_sync(0xFFFFFFFFu, z2b, 1);
    z2b += __shfl_xor_sync(0xFFFFFFFFu, z2b, 2);
    __syncthreads();            // z region dead; safe to reuse as mu buffers

    // ---- prefetch mu chunk 0 ----
    {
        const float4* src = g_mu_p;
#pragma unroll
        for (int j = 0; j < 8; j++) {
            int i = tid + j * THREADS;             // 0..2047
            CP16(sb + (uint32_t)((i >> 3) * 9 + (i & 7)) * 16, src + i);
        }
        CP_COMMIT();
    }

    float best0 = CUDART_INF_F, best1 = CUDART_INF_F;

#pragma unroll 1
    for (int ch = 0; ch < NCHUNKS; ch++) {
        if (ch < NCHUNKS - 1) {
            const float4* src = g_mu_p + (size_t)(ch + 1) * 2048;
            uint32_t dstb = sb + ((ch + 1) & 1) * BUFBYTES;
#pragma unroll
            for (int j = 0; j < 8; j++) {
                int i = tid + j * THREADS;
                CP16(dstb + (uint32_t)((i >> 3) * 9 + (i & 7)) * 16, src + i);
            }
            CP_COMMIT();
            CP_WAIT(1);
        } else {
            CP_WAIT(0);
        }
        __syncthreads();

        const float4* buf = reinterpret_cast<const float4*>(
            smem + (ch & 1) * BUFBYTES);
        float acc[8][4];
#pragma unroll
        for (int nt = 0; nt < 8; nt++)
#pragma unroll
            for (int i = 0; i < 4; i++) acc[nt][i] = 0.f;

#pragma unroll
        for (int kp = 0; kp < 8; kp++) {
#pragma unroll
            for (int nt = 0; nt < 8; nt++) {
                float4 b = buf[nt * 288 + lane * 9 + kp];
                mma_tf32(acc[nt], A[2 * kp],
                         __float_as_uint(b.x), __float_as_uint(b.y));
                mma_tf32(acc[nt], A[2 * kp + 1],
                         __float_as_uint(b.z), __float_as_uint(b.w));
            }
        }

        // fold min(m2[c] - 2*dot)
        const float* m2c = sm2 + ch * NCHUNK;
#pragma unroll
        for (int nt = 0; nt < 8; nt++) {
            float m20 = m2c[nt * 8 + 2 * t];
            float m21 = m2c[nt * 8 + 2 * t + 1];
            best0 = fminf(best0, fmaf(acc[nt][0], -2.f, m20));
            best0 = fminf(best0, fmaf(acc[nt][1], -2.f, m21));
            best1 = fminf(best1, fmaf(acc[nt][2], -2.f, m20));
            best1 = fminf(best1, fmaf(acc[nt][3], -2.f, m21));
        }
        __syncthreads();        // all reads done before buf reuse
    }

    // ---- column-min across quads, then block sum ----
    best0 = fminf(best0, __shfl_xor_sync(0xFFFFFFFFu, best0, 1));
    best0 = fminf(best0, __shfl_xor_sync(0xFFFFFFFFu, best0, 2));
    best1 = fminf(best1, __shfl_xor_sync(0xFFFFFFFFu, best1, 1));
    best1 = fminf(best1, __shfl_xor_sync(0xFFFFFFFFu, best1, 2));

    float contrib = 0.f;
    if (t == 0) {
        contrib  = sqrtf(fmaxf(z2a + best0, 0.f));
        contrib += sqrtf(fmaxf(z2b + best1, 0.f));
    }
#pragma unroll
    for (int o = 16; o; o >>= 1)
        contrib += __shfl_xor_sync(0xFFFFFFFFu, contrib, o);
    if (lane == 0) sred[w] = contrib;
    __syncthreads();
    if (tid == 0) {
        g_partials[blockIdx.x] =
            ((sred[0] + sred[1]) + (sred[2] + sred[3])) +
            ((sred[4] + sred[5]) + (sred[6] + sred[7]));
    }
}

// ---------------------------------------------------------------------------
__global__ void finalize_kernel(float* __restrict__ out) {
    __shared__ float sr[256];
    int tid = threadIdx.x;
    sr[tid] = g_partials[tid] + g_partials[tid + 256];
    __syncthreads();
#pragma unroll
    for (int s = 128; s > 0; s >>= 1) {
        if (tid < s) sr[tid] += sr[tid + s];
        __syncthreads();
    }
    if (tid == 0) out[0] = sr[0] * (1.0f / (float)NPTS);
}

// ---------------------------------------------------------------------------
extern "C" void kernel_launch(void* const* d_in, const int* in_sizes, int n_in,
                              void* d_out, int out_size) {
    const float* z  = (const float*)d_in[0];   // (65536, 1, 128) f32
    const float* mu = (const float*)d_in[1];   // (512, 128) f32
    float* out = (float*)d_out;

    cudaFuncSetAttribute(main_kernel,
                         cudaFuncAttributeMaxDynamicSharedMemorySize, SMEM_BYTES);
    prep_kernel<<<NC / 8, THREADS>>>(mu);
    main_kernel<<<NTILES, THREADS, SMEM_BYTES>>>(z);
    finalize_kernel<<<1, 256>>>(out);
}

// round 10
// speedup vs baseline: 1.0047x; 1.0047x over previous
#include <cuda_runtime.h>
#include <cstdint>
#include <math_constants.h>

#define NPTS    65536
#define DIM     128
#define NC      512
#define MTILE   128
#define NTILES  (NPTS / MTILE)      // 512
#define NCHUNK  64                  // centroids per chunk
#define NCHUNKS (NC / NCHUNK)       // 8
#define THREADS 256
#define ZROW    132                 // padded z row stride (floats)

// Permuted-mu chunk in smem: 2048 float4 data in 9-stride padded slots
#define BUFSLOTS 2304               // (2048/8)*9
#define BUFBYTES (BUFSLOTS * 16)    // 36864
// SMEM: [buf0 | buf1 | sm2(512f) | sred(8f)]   (z stage aliases buf region)
#define OFF_SM2   (2 * BUFBYTES)
#define OFF_SRED  (OFF_SM2 + NC * 4)
#define SMEM_BYTES (OFF_SRED + 64)  // 75840

// Device scratch (no allocation allowed)
__device__ float4 g_mu_p[NC * 32];  // permuted tf32-rounded mu: (c*4+t)*8+kp
__device__ float  g_m2[NC];
__device__ float  g_partials[NTILES];

__device__ __forceinline__ uint32_t smem_u32(const void* p) {
    uint32_t a;
    asm("{ .reg .u64 t; cvta.to.shared.u64 t, %1; cvt.u32.u64 %0, t; }" : "=r"(a) : "l"(p));
    return a;
}
__device__ __forceinline__ uint32_t tf32_rna(float x) {
    uint32_t r;
    asm("cvt.rna.tf32.f32 %0, %1;" : "=r"(r) : "f"(x));
    return r;
}
__device__ __forceinline__ void mma_tf32(float* c, const uint32_t* a,
                                         uint32_t b0, uint32_t b1) {
    asm volatile(
        "mma.sync.aligned.m16n8k8.row.col.f32.tf32.tf32.f32 "
        "{%0,%1,%2,%3}, {%4,%5,%6,%7}, {%8,%9}, {%0,%1,%2,%3};"
        : "+f"(c[0]), "+f"(c[1]), "+f"(c[2]), "+f"(c[3])
        : "r"(a[0]), "r"(a[1]), "r"(a[2]), "r"(a[3]), "r"(b0), "r"(b1));
}
#define CP16(dst, src) \
    asm volatile("cp.async.cg.shared.global [%0], [%1], 16;" :: "r"(dst), "l"(src))
#define CP_COMMIT() asm volatile("cp.async.commit_group;" ::: "memory")
#define CP_WAIT(n)  asm volatile("cp.async.wait_group %0;" :: "n"(n) : "memory")

// ---------------------------------------------------------------------------
// prep: tf32-round mu into permuted layout + m2. One warp per centroid.
// lane -> (t = l&3, kp = l>>2). float4 = {mu[16kp+t], +4, +8, +12} rounded.
// ---------------------------------------------------------------------------
__global__ void prep_kernel(const float* __restrict__ mu) {
    int w = threadIdx.x >> 5, l = threadIdx.x & 31;
    int c = blockIdx.x * 8 + w;
    int t = l & 3, kp = l >> 2;
    const float* row = mu + (size_t)c * DIM;
    float a = __uint_as_float(tf32_rna(row[16 * kp + t]));
    float b = __uint_as_float(tf32_rna(row[16 * kp + t + 4]));
    float e = __uint_as_float(tf32_rna(row[16 * kp + t + 8]));
    float d = __uint_as_float(tf32_rna(row[16 * kp + t + 12]));
    g_mu_p[(size_t)c * 32 + t * 8 + kp] = make_float4(a, b, e, d);
    float s = a * a + b * b + e * e + d * d;
#pragma unroll
    for (int o = 16; o; o >>= 1) s += __shfl_xor_sync(0xFFFFFFFFu, s, o);
    if (l == 0) g_m2[c] = s;
}

// ---------------------------------------------------------------------------
// main: tf32 mma.sync GEMM with vectorized B frags + cp.async double buffer
// ---------------------------------------------------------------------------
__global__ void __launch_bounds__(THREADS, 2)
main_kernel(const float* __restrict__ z) {
    extern __shared__ __align__(16) char smem[];
    const uint32_t sb = smem_u32(smem);
    float* sm2  = reinterpret_cast<float*>(smem + OFF_SM2);
    float* sred = reinterpret_cast<float*>(smem + OFF_SRED);
    float* szf  = reinterpret_cast<float*>(smem);   // z stage aliases bufs

    const int tid = threadIdx.x, w = tid >> 5, lane = tid & 31;
    const int g = lane >> 2, t = lane & 3;
    const int mb = w * 16;

    // ---- stage z tile (raw) into padded smem via cp.async ----
    const float4* zt4 = reinterpret_cast<const float4*>(
        z + (size_t)blockIdx.x * MTILE * DIM);
#pragma unroll
    for (int j = 0; j < 16; j++) {
        int i = tid + j * THREADS;                 // float4 index, 0..4095
        int row = i >> 5, c4 = i & 31;
        CP16(sb + (uint32_t)(row * ZROW + c4 * 4) * 4, zt4 + i);
    }
    CP_COMMIT();
    // overlap: m2 table into smem
#pragma unroll
    for (int j = 0; j < 2; j++) sm2[tid + j * THREADS] = g_m2[tid + j * THREADS];
    CP_WAIT(0);
    __syncthreads();

    // ---- A fragments (tf32-rounded) + z2 from registers ----
    uint32_t A[16][4];
#pragma unroll
    for (int kk = 0; kk < 16; kk++) {
        A[kk][0] = tf32_rna(szf[(mb + g    ) * ZROW + kk * 8 + t    ]);
        A[kk][1] = tf32_rna(szf[(mb + g + 8) * ZROW + kk * 8 + t    ]);
        A[kk][2] = tf32_rna(szf[(mb + g    ) * ZROW + kk * 8 + t + 4]);
        A[kk][3] = tf32_rna(szf[(mb + g + 8) * ZROW + kk * 8 + t + 4]);
    }
    float z2a = 0.f, z2b = 0.f;
#pragma unroll
    for (int kk = 0; kk < 16; kk++) {
        float a0 = __uint_as_float(A[kk][0]), a2 = __uint_as_float(A[kk][2]);
        float a1 = __uint_as_float(A[kk][1]), a3 = __uint_as_float(A[kk][3]);
        z2a += a0 * a0 + a2 * a2;
        z2b += a1 * a1 + a3 * a3;
    }
    z2a += __shfl_xor_sync(0xFFFFFFFFu, z2a, 1);
    z2a += __shfl_xor_sync(0xFFFFFFFFu, z2a, 2);
    z2b += __shfl_xor_sync(0xFFFFFFFFu, z2b, 1);
    z2b += __shfl_xor_sync(0xFFFFFFFFu, z2b, 2);
    __syncthreads();            // z region dead; safe to reuse as mu buffers

    // ---- prefetch mu chunk 0 ----
    {
        const float4* src = g_mu_p;
#pragma unroll
        for (int j = 0; j < 8; j++) {
            int i = tid + j * THREADS;             // 0..2047
            CP16(sb + (uint32_t)((i >> 3) * 9 + (i & 7)) * 16, src + i);
        }
        CP_COMMIT();
    }

    float best0 = CUDART_INF_F, best1 = CUDART_INF_F;

#pragma unroll 1
    for (int ch = 0; ch < NCHUNKS; ch++) {
        if (ch < NCHUNKS - 1) {
            const float4* src = g_mu_p + (size_t)(ch + 1) * 2048;
            uint32_t dstb = sb + ((ch + 1) & 1) * BUFBYTES;
#pragma unroll
            for (int j = 0; j < 8; j++) {
                int i = tid + j * THREADS;
                CP16(dstb + (uint32_t)((i >> 3) * 9 + (i & 7)) * 16, src + i);
            }
            CP_COMMIT();
            CP_WAIT(1);
        } else {
            CP_WAIT(0);
        }
        __syncthreads();

        const float4* buf = reinterpret_cast<const float4*>(
            smem + (ch & 1) * BUFBYTES);
        float acc[8][4];
#pragma unroll
        for (int nt = 0; nt < 8; nt++)
#pragma unroll
            for (int i = 0; i < 4; i++) acc[nt][i] = 0.f;

#pragma unroll
        for (int kp = 0; kp < 8; kp++) {
#pragma unroll
            for (int nt = 0; nt < 8; nt++) {
                float4 b = buf[nt * 288 + lane * 9 + kp];
                mma_tf32(acc[nt], A[2 * kp],
                         __float_as_uint(b.x), __float_as_uint(b.y));
                mma_tf32(acc[nt], A[2 * kp + 1],
                         __float_as_uint(b.z), __float_as_uint(b.w));
            }
        }

        // fold min(m2[c] - 2*dot)
        const float* m2c = sm2 + ch * NCHUNK;
#pragma unroll
        for (int nt = 0; nt < 8; nt++) {
            float m20 = m2c[nt * 8 + 2 * t];
            float m21 = m2c[nt * 8 + 2 * t + 1];
            best0 = fminf(best0, fmaf(acc[nt][0], -2.f, m20));
            best0 = fminf(best0, fmaf(acc[nt][1], -2.f, m21));
            best1 = fminf(best1, fmaf(acc[nt][2], -2.f, m20));
            best1 = fminf(best1, fmaf(acc[nt][3], -2.f, m21));
        }
        __syncthreads();        // all reads done before buf reuse
    }

    // ---- column-min across quads, then block sum ----
    best0 = fminf(best0, __shfl_xor_sync(0xFFFFFFFFu, best0, 1));
    best0 = fminf(best0, __shfl_xor_sync(0xFFFFFFFFu, best0, 2));
    best1 = fminf(best1, __shfl_xor_sync(0xFFFFFFFFu, best1, 1));
    best1 = fminf(best1, __shfl_xor_sync(0xFFFFFFFFu, best1, 2));

    float contrib = 0.f;
    if (t == 0) {
        contrib  = sqrtf(fmaxf(z2a + best0, 0.f));
        contrib += sqrtf(fmaxf(z2b + best1, 0.f));
    }
#pragma unroll
    for (int o = 16; o; o >>= 1)
        contrib += __shfl_xor_sync(0xFFFFFFFFu, contrib, o);
    if (lane == 0) sred[w] = contrib;
    __syncthreads();
    if (tid == 0) {
        g_partials[blockIdx.x] =
            ((sred[0] + sred[1]) + (sred[2] + sred[3])) +
            ((sred[4] + sred[5]) + (sred[6] + sred[7]));
    }
}

// ---------------------------------------------------------------------------
__global__ void finalize_kernel(float* __restrict__ out) {
    __shared__ float sr[256];
    int tid = threadIdx.x;
    sr[tid] = g_partials[tid] + g_partials[tid + 256];
    __syncthreads();
#pragma unroll
    for (int s = 128; s > 0; s >>= 1) {
        if (tid < s) sr[tid] += sr[tid + s];
        __syncthreads();
    }
    if (tid == 0) out[0] = sr[0] * (1.0f / (float)NPTS);
}

// ---------------------------------------------------------------------------
extern "C" void kernel_launch(void* const* d_in, const int* in_sizes, int n_in,
                              void* d_out, int out_size) {
    const float* z  = (const float*)d_in[0];   // (65536, 1, 128) f32
    const float* mu = (const float*)d_in[1];   // (512, 128) f32
    float* out = (float*)d_out;

    cudaFuncSetAttribute(main_kernel,
                         cudaFuncAttributeMaxDynamicSharedMemorySize, SMEM_BYTES);
    prep_kernel<<<NC / 8, THREADS>>>(mu);
    main_kernel<<<NTILES, THREADS, SMEM_BYTES>>>(z);
    finalize_kernel<<<1, 256>>>(out);
}

// round 11
// speedup vs baseline: 1.0093x; 1.0047x over previous
#include <cuda_runtime.h>
#include <cstdint>
#include <math_constants.h>

#define NPTS    65536
#define DIM     128
#define NC      512
#define MTILE   128
#define NTILES  (NPTS / MTILE)      // 512
#define NCHUNK  64                  // centroids per chunk
#define NCHUNKS (NC / NCHUNK)       // 8
#define THREADS 256
#define ZROW    132                 // padded z row stride (floats)

// Permuted-mu chunk in smem: 2048 float4 data in 9-stride padded slots
#define BUFSLOTS 2304               // (2048/8)*9
#define BUFBYTES (BUFSLOTS * 16)    // 36864
// SMEM: [buf0 | buf1 | sm2(512f) | sred(8f)]   (z stage aliases buf region)
#define OFF_SM2   (2 * BUFBYTES)
#define OFF_SRED  (OFF_SM2 + NC * 4)
#define SMEM_BYTES (OFF_SRED + 64)  // 75840

// Device scratch (no allocation allowed)
__device__ float4 g_mu_p[NC * 32];  // permuted tf32-rounded mu: (c*4+t)*8+kp
__device__ float  g_m2[NC];
__device__ float  g_partials[NTILES];

__device__ __forceinline__ uint32_t smem_u32(const void* p) {
    uint32_t a;
    asm("{ .reg .u64 t; cvta.to.shared.u64 t, %1; cvt.u32.u64 %0, t; }" : "=r"(a) : "l"(p));
    return a;
}
__device__ __forceinline__ uint32_t tf32_rna(float x) {
    uint32_t r;
    asm("cvt.rna.tf32.f32 %0, %1;" : "=r"(r) : "f"(x));
    return r;
}
__device__ __forceinline__ void mma_tf32(float* c, const uint32_t* a,
                                         uint32_t b0, uint32_t b1) {
    asm volatile(
        "mma.sync.aligned.m16n8k8.row.col.f32.tf32.tf32.f32 "
        "{%0,%1,%2,%3}, {%4,%5,%6,%7}, {%8,%9}, {%0,%1,%2,%3};"
        : "+f"(c[0]), "+f"(c[1]), "+f"(c[2]), "+f"(c[3])
        : "r"(a[0]), "r"(a[1]), "r"(a[2]), "r"(a[3]), "r"(b0), "r"(b1));
}
#define CP16(dst, src) \
    asm volatile("cp.async.cg.shared.global [%0], [%1], 16;" :: "r"(dst), "l"(src))
#define CP_COMMIT() asm volatile("cp.async.commit_group;" ::: "memory")
#define CP_WAIT(n)  asm volatile("cp.async.wait_group %0;" :: "n"(n) : "memory")

// ---------------------------------------------------------------------------
// prep: tf32-round mu into permuted layout + m2. One warp per centroid.
// lane -> (t = l&3, kp = l>>2). float4 = {mu[16kp+t], +4, +8, +12} rounded.
// ---------------------------------------------------------------------------
__global__ void prep_kernel(const float* __restrict__ mu) {
    int w = threadIdx.x >> 5, l = threadIdx.x & 31;
    int c = blockIdx.x * 8 + w;
    int t = l & 3, kp = l >> 2;
    const float* row = mu + (size_t)c * DIM;
    float a = __uint_as_float(tf32_rna(row[16 * kp + t]));
    float b = __uint_as_float(tf32_rna(row[16 * kp + t + 4]));
    float e = __uint_as_float(tf32_rna(row[16 * kp + t + 8]));
    float d = __uint_as_float(tf32_rna(row[16 * kp + t + 12]));
    g_mu_p[(size_t)c * 32 + t * 8 + kp] = make_float4(a, b, e, d);
    float s = a * a + b * b + e * e + d * d;
#pragma unroll
    for (int o = 16; o; o >>= 1) s += __shfl_xor_sync(0xFFFFFFFFu, s, o);
    if (l == 0) g_m2[c] = s;
}

// ---------------------------------------------------------------------------
// main: tf32 mma.sync GEMM with vectorized B frags + cp.async double buffer
// ---------------------------------------------------------------------------
__global__ void __launch_bounds__(THREADS, 2)
main_kernel(const float* __restrict__ z) {
    extern __shared__ __align__(16) char smem[];
    const uint32_t sb = smem_u32(smem);
    float* sm2  = reinterpret_cast<float*>(smem + OFF_SM2);
    float* sred = reinterpret_cast<float*>(smem + OFF_SRED);
    float* szf  = reinterpret_cast<float*>(smem);   // z stage aliases bufs

    const int tid = threadIdx.x, w = tid >> 5, lane = tid & 31;
    const int g = lane >> 2, t = lane & 3;
    const int mb = w * 16;

    // ---- stage z tile (raw) into padded smem via cp.async ----
    const float4* zt4 = reinterpret_cast<const float4*>(
        z + (size_t)blockIdx.x * MTILE * DIM);
#pragma unroll
    for (int j = 0; j < 16; j++) {
        int i = tid + j * THREADS;                 // float4 index, 0..4095
        int row = i >> 5, c4 = i & 31;
        CP16(sb + (uint32_t)(row * ZROW + c4 * 4) * 4, zt4 + i);
    }
    CP_COMMIT();
    // overlap: m2 table into smem
#pragma unroll
    for (int j = 0; j < 2; j++) sm2[tid + j * THREADS] = g_m2[tid + j * THREADS];
    CP_WAIT(0);
    __syncthreads();

    // ---- A fragments (tf32-rounded) + z2 from registers ----
    uint32_t A[16][4];
#pragma unroll
    for (int kk = 0; kk < 16; kk++) {
        A[kk][0] = tf32_rna(szf[(mb + g    ) * ZROW + kk * 8 + t    ]);
        A[kk][1] = tf32_rna(szf[(mb + g + 8) * ZROW + kk * 8 + t    ]);
        A[kk][2] = tf32_rna(szf[(mb + g    ) * ZROW + kk * 8 + t + 4]);
        A[kk][3] = tf32_rna(szf[(mb + g + 8) * ZROW + kk * 8 + t + 4]);
    }
    float z2a = 0.f, z2b = 0.f;
#pragma unroll
    for (int kk = 0; kk < 16; kk++) {
        float a0 = __uint_as_float(A[kk][0]), a2 = __uint_as_float(A[kk][2]);
        float a1 = __uint_as_float(A[kk][1]), a3 = __uint_as_float(A[kk][3]);
        z2a += a0 * a0 + a2 * a2;
        z2b += a1 * a1 + a3 * a3;
    }
    z2a += __shfl_xor_sync(0xFFFFFFFFu, z2a, 1);
    z2a += __shfl_xor_sync(0xFFFFFFFFu, z2a, 2);
    z2b += __shfl_xor_sync(0xFFFFFFFFu, z2b, 1);
    z2b += __shfl_xor_sync(0xFFFFFFFFu, z2b, 2);
    __syncthreads();            // z region dead; safe to reuse as mu buffers

    // ---- prefetch mu chunk 0 ----
    {
        const float4* src = g_mu_p;
#pragma unroll
        for (int j = 0; j < 8; j++) {
            int i = tid + j * THREADS;             // 0..2047
            CP16(sb + (uint32_t)((i >> 3) * 9 + (i & 7)) * 16, src + i);
        }
        CP_COMMIT();
    }

    float best0 = CUDART_INF_F, best1 = CUDART_INF_F;

#pragma unroll 1
    for (int ch = 0; ch < NCHUNKS; ch++) {
        if (ch < NCHUNKS - 1) {
            const float4* src = g_mu_p + (size_t)(ch + 1) * 2048;
            uint32_t dstb = sb + ((ch + 1) & 1) * BUFBYTES;
#pragma unroll
            for (int j = 0; j < 8; j++) {
                int i = tid + j * THREADS;
                CP16(dstb + (uint32_t)((i >> 3) * 9 + (i & 7)) * 16, src + i);
            }
            CP_COMMIT();
            CP_WAIT(1);
        } else {
            CP_WAIT(0);
        }
        __syncthreads();

        const float4* buf = reinterpret_cast<const float4*>(
            smem + (ch & 1) * BUFBYTES);
        float acc[8][4];
#pragma unroll
        for (int nt = 0; nt < 8; nt++)
#pragma unroll
            for (int i = 0; i < 4; i++) acc[nt][i] = 0.f;

#pragma unroll
        for (int kp = 0; kp < 8; kp++) {
#pragma unroll
            for (int nt = 0; nt < 8; nt++) {
                float4 b = buf[nt * 288 + lane * 9 + kp];
                mma_tf32(acc[nt], A[2 * kp],
                         __float_as_uint(b.x), __float_as_uint(b.y));
                mma_tf32(acc[nt], A[2 * kp + 1],
                         __float_as_uint(b.z), __float_as_uint(b.w));
            }
        }

        // fold min(m2[c] - 2*dot)
        const float* m2c = sm2 + ch * NCHUNK;
#pragma unroll
        for (int nt = 0; nt < 8; nt++) {
            float m20 = m2c[nt * 8 + 2 * t];
            float m21 = m2c[nt * 8 + 2 * t + 1];
            best0 = fminf(best0, fmaf(acc[nt][0], -2.f, m20));
            best0 = fminf(best0, fmaf(acc[nt][1], -2.f, m21));
            best1 = fminf(best1, fmaf(acc[nt][2], -2.f, m20));
            best1 = fminf(best1, fmaf(acc[nt][3], -2.f, m21));
        }
        __syncthreads();        // all reads done before buf reuse
    }

    // ---- column-min across quads, then block sum ----
    best0 = fminf(best0, __shfl_xor_sync(0xFFFFFFFFu, best0, 1));
    best0 = fminf(best0, __shfl_xor_sync(0xFFFFFFFFu, best0, 2));
    best1 = fminf(best1, __shfl_xor_sync(0xFFFFFFFFu, best1, 1));
    best1 = fminf(best1, __shfl_xor_sync(0xFFFFFFFFu, best1, 2));

    float contrib = 0.f;
    if (t == 0) {
        contrib  = sqrtf(fmaxf(z2a + best0, 0.f));
        contrib += sqrtf(fmaxf(z2b + best1, 0.f));
    }
#pragma unroll
    for (int o = 16; o; o >>= 1)
        contrib += __shfl_xor_sync(0xFFFFFFFFu, contrib, o);
    if (lane == 0) sred[w] = contrib;
    __syncthreads();
    if (tid == 0) {
        g_partials[blockIdx.x] =
            ((sred[0] + sred[1]) + (sred[2] + sred[3])) +
            ((sred[4] + sred[5]) + (sred[6] + sred[7]));
    }
}

// ---------------------------------------------------------------------------
__global__ void finalize_kernel(float* __restrict__ out) {
    __shared__ float sr[256];
    int tid = threadIdx.x;
    sr[tid] = g_partials[tid] + g_partials[tid + 256];
    __syncthreads();
#pragma unroll
    for (int s = 128; s > 0; s >>= 1) {
        if (tid < s) sr[tid] += sr[tid + s];
        __syncthreads();
    }
    if (tid == 0) out[0] = sr[0] * (1.0f / (float)NPTS);
}

// ---------------------------------------------------------------------------
extern "C" void kernel_launch(void* const* d_in, const int* in_sizes, int n_in,
                              void* d_out, int out_size) {
    const float* z  = (const float*)d_in[0];   // (65536, 1, 128) f32
    const float* mu = (const float*)d_in[1];   // (512, 128) f32
    float* out = (float*)d_out;

    cudaFuncSetAttribute(main_kernel,
                         cudaFuncAttributeMaxDynamicSharedMemorySize, SMEM_BYTES);
    prep_kernel<<<NC / 8, THREADS>>>(mu);
    main_kernel<<<NTILES, THREADS, SMEM_BYTES>>>(z);
    finalize_kernel<<<1, 256>>>(out);
}